// round 6
// baseline (speedup 1.0000x reference)
#include <cuda_runtime.h>
#include <cuda_bf16.h>
#include <cstdint>

// Problem constants
#define C_DIM   1024
#define TC3     3072          // 3*C
#define T_SEQ   2048
#define B_SZ    4
#define H_NUM   16
#define HD      64
#define M_ROWS  (B_SZ * T_SEQ)   // 8192

// Scratch (allocation-free rule: __device__ globals)
__device__ float g_qkv[(size_t)M_ROWS * TC3];          // [B*T, 3C] (tf32-rounded)
__device__ float g_y  [(size_t)M_ROWS * C_DIM];        // [B*T, C] (tf32-rounded)
__device__ float g_xr [(size_t)M_ROWS * C_DIM];        // tf32-rounded x
__device__ float g_wt [(size_t)TC3 * C_DIM + (size_t)C_DIM * C_DIM]; // W^T (tf32-rounded)

// ---------------------------------------------------------------------------
// Helpers (arch-portable PTX only: cp.async + mma.sync, both sm_80+)
// ---------------------------------------------------------------------------
__device__ __forceinline__ uint32_t smem_u32(const void* p) {
    uint32_t a;
    asm("{ .reg .u64 t; cvta.to.shared.u64 t, %1; cvt.u32.u64 %0, t; }" : "=r"(a) : "l"(p));
    return a;
}

__device__ __forceinline__ float tf32r(float x) {
    uint32_t r;
    asm("cvt.rn.tf32.f32 %0, %1;" : "=r"(r) : "f"(x));
    return __uint_as_float(r);
}

__device__ __forceinline__ void cpasync16(uint32_t s, const void* g) {
    asm volatile("cp.async.cg.shared.global [%0], [%1], 16;" :: "r"(s), "l"(g));
}
#define CP_COMMIT() asm volatile("cp.async.commit_group;" ::: "memory")
#define CP_WAIT(n)  asm volatile("cp.async.wait_group %0;" :: "n"(n) : "memory")

// mma.sync m16n8k8 tf32: D = A*B + C (fp32 accum)
__device__ __forceinline__ void mma_tf32(float* c, const uint32_t* a, const uint32_t* b) {
    asm volatile(
        "mma.sync.aligned.m16n8k8.row.col.f32.tf32.tf32.f32 "
        "{%0,%1,%2,%3}, {%4,%5,%6,%7}, {%8,%9}, {%0,%1,%2,%3};"
        : "+f"(c[0]), "+f"(c[1]), "+f"(c[2]), "+f"(c[3])
        : "r"(a[0]), "r"(a[1]), "r"(a[2]), "r"(a[3]), "r"(b[0]), "r"(b[1]));
}

// Fast exp2 on the FMA pipe (no MUFU). Valid for z <= 0; clamps at -126.
__device__ __forceinline__ float exp2_fast(float z) {
    z = fmaxf(z, -126.f);
    float r = __fadd_rn(z, 12582912.f);            // round z to nearest int
    float f = z - __fadd_rn(r, -12582912.f);       // frac in [-0.5, 0.5]
    int   n = __float_as_int(r) - 0x4B400000;      // integer part
    float p = 1.f + f * (0.69314718f + f * (0.24022651f +
              f * (0.05550411f + f * 0.00961813f)));
    return __int_as_float(__float_as_int(p) + (n << 23));
}

// ---------------------------------------------------------------------------
// tf32 mma.sync GEMM: C[M,N] = A[M,K] @ Bt[N,K]^T + bias
// CTA 128x128, BK=16, 256 threads = 8 warps (2m x 4n), warp tile 64x32.
// 4-stage cp.async pipeline (3 k-tiles in flight), 1 barrier per k-tile.
// round_out!=0 -> store tf32-rounded output.
// ---------------------------------------------------------------------------
#define BM 128
#define BN 128
#define BK 16
#define LDST 20          // floats; row stride 80B (16B-aligned, conflict-free LDS)
#define NSTAGE 4
#define STG_FLOATS ((BM + BN) * LDST)                 // 5120 floats / stage
#define GEMM_SMEM  (NSTAGE * STG_FLOATS * 4)          // 81920 B

__global__ __launch_bounds__(256, 2)
void gemm_tf32_mma(const float* __restrict__ A, const float* __restrict__ Bt,
                   const float* __restrict__ bias, float* __restrict__ C,
                   int M, int N, int K, int round_out)
{
    extern __shared__ float sm[];
    // stage s: A at sm + s*STG_FLOATS, B at +BM*LDST
    const int tid  = threadIdx.x;
    const int wid  = tid >> 5;
    const int lane = tid & 31;
    const int wm   = wid & 1;        // 0..1 (64-row slab)
    const int wn   = wid >> 1;       // 0..3 (32-col slab)
    const int m0   = blockIdx.y * BM;
    const int n0   = blockIdx.x * BN;

    const int lrow = lane >> 2;      // 0..7
    const int lcol = lane & 3;       // 0..3

    float acc[4][4][4];
    #pragma unroll
    for (int mi = 0; mi < 4; mi++)
        #pragma unroll
        for (int ni = 0; ni < 4; ni++)
            #pragma unroll
            for (int r = 0; r < 4; r++) acc[mi][ni][r] = 0.f;

    const int nkt = K / BK;          // 64

    auto issue = [&](int s, int kt) {
        float* as = sm + s * STG_FLOATS;
        float* bs = as + BM * LDST;
        const int k0 = kt * BK;
        #pragma unroll
        for (int i = 0; i < 2; i++) {
            int c   = tid + i * 256;      // 0..511
            int row = c >> 2;
            int col = (c & 3) * 4;
            cpasync16(smem_u32(as + row * LDST + col),
                      A + (size_t)(m0 + row) * K + k0 + col);
            cpasync16(smem_u32(bs + row * LDST + col),
                      Bt + (size_t)(n0 + row) * K + k0 + col);
        }
        CP_COMMIT();
    };

    // prologue: 3 stages in flight
    issue(0, 0); issue(1, 1); issue(2, 2);

    for (int kt = 0; kt < nkt; kt++) {
        const int s = kt & (NSTAGE - 1);
        CP_WAIT(2);                    // oldest (kt) landed
        __syncthreads();               // visible to all; stage kt-1 reads done
        if (kt + 3 < nkt) issue((kt + 3) & (NSTAGE - 1), kt + 3);

        const float* as = sm + s * STG_FLOATS;
        const float* bs = as + BM * LDST;

        #pragma unroll
        for (int ks = 0; ks < 2; ks++) {
            const int kc = ks * 8 + lcol;
            uint32_t af[4][4], bf[4][2];
            #pragma unroll
            for (int mi = 0; mi < 4; mi++) {
                const float* ap = as + (wm * 64 + mi * 16 + lrow) * LDST + kc;
                af[mi][0] = __float_as_uint(ap[0]);
                af[mi][1] = __float_as_uint(ap[8 * LDST]);
                af[mi][2] = __float_as_uint(ap[4]);
                af[mi][3] = __float_as_uint(ap[8 * LDST + 4]);
            }
            #pragma unroll
            for (int ni = 0; ni < 4; ni++) {
                const float* bp = bs + (wn * 32 + ni * 8 + lrow) * LDST + kc;
                bf[ni][0] = __float_as_uint(bp[0]);
                bf[ni][1] = __float_as_uint(bp[4]);
            }
            #pragma unroll
            for (int mi = 0; mi < 4; mi++)
                #pragma unroll
                for (int ni = 0; ni < 4; ni++)
                    mma_tf32(acc[mi][ni], af[mi], bf[ni]);
        }
    }

    // epilogue: bias + store
    #pragma unroll
    for (int mi = 0; mi < 4; mi++) {
        const int row_a = m0 + wm * 64 + mi * 16 + lrow;
        #pragma unroll
        for (int ni = 0; ni < 4; ni++) {
            const int col = n0 + wn * 32 + ni * 8 + lcol * 2;
            const float2 b2 = *reinterpret_cast<const float2*>(&bias[col]);
            float2 o0, o1;
            o0.x = acc[mi][ni][0] + b2.x;
            o0.y = acc[mi][ni][1] + b2.y;
            o1.x = acc[mi][ni][2] + b2.x;
            o1.y = acc[mi][ni][3] + b2.y;
            if (round_out) {
                o0.x = tf32r(o0.x); o0.y = tf32r(o0.y);
                o1.x = tf32r(o1.x); o1.y = tf32r(o1.y);
            }
            *reinterpret_cast<float2*>(&C[(size_t)row_a * N + col])       = o0;
            *reinterpret_cast<float2*>(&C[(size_t)(row_a + 8) * N + col]) = o1;
        }
    }
}

// ---------------------------------------------------------------------------
// Prep kernels
// ---------------------------------------------------------------------------
__global__ __launch_bounds__(256)
void round_copy_kernel(const float* __restrict__ in, float* __restrict__ out, int n4)
{
    int i = blockIdx.x * blockDim.x + threadIdx.x;
    for (; i < n4; i += gridDim.x * blockDim.x) {
        float4 v = reinterpret_cast<const float4*>(in)[i];
        v.x = tf32r(v.x); v.y = tf32r(v.y); v.z = tf32r(v.z); v.w = tf32r(v.w);
        reinterpret_cast<float4*>(out)[i] = v;
    }
}

__global__ __launch_bounds__(256)
void transpose_round_kernel(const float* __restrict__ in, float* __restrict__ out,
                            int R, int Ccols)
{
    __shared__ float t[32][33];
    const int bx = blockIdx.x * 32;
    const int by = blockIdx.y * 32;
    const int tx = threadIdx.x, ty = threadIdx.y;
    #pragma unroll
    for (int i = 0; i < 32; i += 8)
        t[ty + i][tx] = in[(size_t)(by + ty + i) * Ccols + bx + tx];
    __syncthreads();
    #pragma unroll
    for (int i = 0; i < 32; i += 8)
        out[(size_t)(bx + ty + i) * R + by + tx] = tf32r(t[tx][ty + i]);
}

// ---------------------------------------------------------------------------
// Flash attention, tf32 mma.sync + FMA-pipe exp2, causal. (proven in R4/R5)
// ---------------------------------------------------------------------------
#define AT_STRIDE 68                     // 64 + 4 pad
#define KV_TILE   (64 * AT_STRIDE)
#define ATT_SMEM  ((4 * KV_TILE + 128 * AT_STRIDE) * 4)

__global__ __launch_bounds__(256, 2)
void flash_attn_mma(const float* __restrict__ qkv, float* __restrict__ y)
{
    extern __shared__ float smf[];
    float* Ksm = smf;                    // [2][64][AT_STRIDE]
    float* Vsm = smf + 2 * KV_TILE;      // [2][64][AT_STRIDE]
    float* PQ  = smf + 4 * KV_TILE;      // [128][AT_STRIDE]

    const int qt = (int)gridDim.x - 1 - (int)blockIdx.x;  // heavy tiles first
    const int bh = blockIdx.y;
    const int b  = bh >> 4;
    const int h  = bh & 15;

    const int tid  = threadIdx.x;
    const int w    = tid >> 5;
    const int lane = tid & 31;
    const int lrow = lane >> 2;
    const int lcol = lane & 3;
    const int w16  = w * 16;

    const float SC = 0.1803368801f;      // 0.125 * log2(e)

    const float* qbase = qkv + (size_t)(b * T_SEQ + qt * 128) * TC3 + h * HD;
    const float* kbase = qkv + (size_t)(b * T_SEQ) * TC3 + C_DIM     + h * HD;
    const float* vbase = qkv + (size_t)(b * T_SEQ) * TC3 + 2 * C_DIM + h * HD;

    const int nkt = 2 * qt + 2;

    auto issue_kv = [&](int kt, int buf) {
        float* kd = Ksm + buf * KV_TILE;
        float* vd = Vsm + buf * KV_TILE;
        const float* ks = kbase + (size_t)(kt * 64) * TC3;
        const float* vs = vbase + (size_t)(kt * 64) * TC3;
        #pragma unroll
        for (int i = 0; i < 4; i++) {
            int c   = tid + i * 256;
            int row = c >> 4;
            int col = (c & 15) * 4;
            cpasync16(smem_u32(kd + row * AT_STRIDE + col), ks + (size_t)row * TC3 + col);
            cpasync16(smem_u32(vd + row * AT_STRIDE + col), vs + (size_t)row * TC3 + col);
        }
        CP_COMMIT();
    };

    #pragma unroll
    for (int i = 0; i < 8; i++) {
        int c   = tid + i * 256;
        int row = c >> 4;
        int col = (c & 15) * 4;
        cpasync16(smem_u32(PQ + row * AT_STRIDE + col), qbase + (size_t)row * TC3 + col);
    }
    CP_COMMIT();
    issue_kv(0, 0);
    CP_WAIT(1);
    __syncthreads();

    uint32_t qf[8][4];
    #pragma unroll
    for (int ks = 0; ks < 8; ks++) {
        const float* q0 = PQ + (w16 + lrow) * AT_STRIDE + ks * 8 + lcol;
        const float* q1 = q0 + 8 * AT_STRIDE;
        qf[ks][0] = __float_as_uint(q0[0]);
        qf[ks][1] = __float_as_uint(q1[0]);
        qf[ks][2] = __float_as_uint(q0[4]);
        qf[ks][3] = __float_as_uint(q1[4]);
    }
    __syncthreads();

    float oacc[8][4];
    #pragma unroll
    for (int nt = 0; nt < 8; nt++)
        #pragma unroll
        for (int r = 0; r < 4; r++) oacc[nt][r] = 0.f;
    float m0 = -1e30f, m1 = -1e30f, l0 = 0.f, l1 = 0.f;

    const int gr0 = qt * 128 + w16 + lrow;
    const int gr1 = gr0 + 8;

    for (int kt = 0; kt < nkt; kt++) {
        const int buf = kt & 1;
        if (kt + 1 < nkt) { issue_kv(kt + 1, buf ^ 1); CP_WAIT(1); }
        else              { CP_WAIT(0); }
        __syncthreads();

        const float* kb = Ksm + buf * KV_TILE;
        const float* vb = Vsm + buf * KV_TILE;

        float s[8][4];
        #pragma unroll
        for (int nt = 0; nt < 8; nt++)
            #pragma unroll
            for (int r = 0; r < 4; r++) s[nt][r] = 0.f;

        #pragma unroll
        for (int ks = 0; ks < 8; ks++) {
            #pragma unroll
            for (int nt = 0; nt < 8; nt++) {
                const float* kp = kb + (nt * 8 + lrow) * AT_STRIDE + ks * 8 + lcol;
                uint32_t bf[2];
                bf[0] = __float_as_uint(kp[0]);
                bf[1] = __float_as_uint(kp[4]);
                mma_tf32(s[nt], qf[ks], bf);
            }
        }

        const bool needmask = (kt >= 2 * qt);
        #pragma unroll
        for (int nt = 0; nt < 8; nt++) {
            const int ck = kt * 64 + nt * 8 + 2 * lcol;
            s[nt][0] *= SC; s[nt][1] *= SC; s[nt][2] *= SC; s[nt][3] *= SC;
            if (needmask) {
                if (ck     > gr0) s[nt][0] = -1e30f;
                if (ck + 1 > gr0) s[nt][1] = -1e30f;
                if (ck     > gr1) s[nt][2] = -1e30f;
                if (ck + 1 > gr1) s[nt][3] = -1e30f;
            }
        }

        float mx0 = -1e30f, mx1 = -1e30f;
        #pragma unroll
        for (int nt = 0; nt < 8; nt++) {
            mx0 = fmaxf(mx0, fmaxf(s[nt][0], s[nt][1]));
            mx1 = fmaxf(mx1, fmaxf(s[nt][2], s[nt][3]));
        }
        mx0 = fmaxf(mx0, __shfl_xor_sync(0xffffffffu, mx0, 1));
        mx0 = fmaxf(mx0, __shfl_xor_sync(0xffffffffu, mx0, 2));
        mx1 = fmaxf(mx1, __shfl_xor_sync(0xffffffffu, mx1, 1));
        mx1 = fmaxf(mx1, __shfl_xor_sync(0xffffffffu, mx1, 2));

        const float mn0 = fmaxf(m0, mx0);
        const float mn1 = fmaxf(m1, mx1);
        const float a0  = exp2_fast(m0 - mn0);
        const float a1  = exp2_fast(m1 - mn1);
        m0 = mn0; m1 = mn1;

        float rs0 = 0.f, rs1 = 0.f;
        #pragma unroll
        for (int nt = 0; nt < 8; nt++) {
            s[nt][0] = exp2_fast(s[nt][0] - mn0);
            s[nt][1] = exp2_fast(s[nt][1] - mn0);
            s[nt][2] = exp2_fast(s[nt][2] - mn1);
            s[nt][3] = exp2_fast(s[nt][3] - mn1);
            rs0 += s[nt][0] + s[nt][1];
            rs1 += s[nt][2] + s[nt][3];
        }
        rs0 += __shfl_xor_sync(0xffffffffu, rs0, 1);
        rs0 += __shfl_xor_sync(0xffffffffu, rs0, 2);
        rs1 += __shfl_xor_sync(0xffffffffu, rs1, 1);
        rs1 += __shfl_xor_sync(0xffffffffu, rs1, 2);
        l0 = l0 * a0 + rs0;
        l1 = l1 * a1 + rs1;

        #pragma unroll
        for (int nt = 0; nt < 8; nt++) {
            oacc[nt][0] *= a0; oacc[nt][1] *= a0;
            oacc[nt][2] *= a1; oacc[nt][3] *= a1;
        }

        #pragma unroll
        for (int nt = 0; nt < 8; nt++) {
            float* p0 = PQ + (w16 + lrow) * AT_STRIDE + nt * 8 + 2 * lcol;
            *reinterpret_cast<float2*>(p0) =
                make_float2(tf32r(s[nt][0]), tf32r(s[nt][1]));
            *reinterpret_cast<float2*>(p0 + 8 * AT_STRIDE) =
                make_float2(tf32r(s[nt][2]), tf32r(s[nt][3]));
        }
        __syncwarp();

        #pragma unroll
        for (int ks = 0; ks < 8; ks++) {
            uint32_t af[4];
            const float* p0 = PQ + (w16 + lrow) * AT_STRIDE + ks * 8 + lcol;
            const float* p1 = p0 + 8 * AT_STRIDE;
            af[0] = __float_as_uint(p0[0]);
            af[1] = __float_as_uint(p1[0]);
            af[2] = __float_as_uint(p0[4]);
            af[3] = __float_as_uint(p1[4]);
            #pragma unroll
            for (int nt = 0; nt < 8; nt++) {
                const float* vp = vb + (ks * 8 + lcol) * AT_STRIDE + nt * 8 + lrow;
                uint32_t bf[2];
                bf[0] = __float_as_uint(vp[0]);
                bf[1] = __float_as_uint(vp[4 * AT_STRIDE]);
                mma_tf32(oacc[nt], af, bf);
            }
        }
        __syncthreads();
    }

    const float inv0 = 1.f / l0;
    const float inv1 = 1.f / l1;
    float* y0 = y + (size_t)(b * T_SEQ + gr0) * C_DIM + h * HD;
    #pragma unroll
    for (int nt = 0; nt < 8; nt++) {
        const int col = nt * 8 + 2 * lcol;
        *reinterpret_cast<float2*>(y0 + (size_t)0 * C_DIM + col) =
            make_float2(tf32r(oacc[nt][0] * inv0), tf32r(oacc[nt][1] * inv0));
        *reinterpret_cast<float2*>(y0 + (size_t)8 * C_DIM + col) =
            make_float2(tf32r(oacc[nt][2] * inv1), tf32r(oacc[nt][3] * inv1));
    }
}

// ---------------------------------------------------------------------------
extern "C" void kernel_launch(void* const* d_in, const int* in_sizes, int n_in,
                              void* d_out, int out_size)
{
    const float* x      = (const float*)d_in[0];
    const float* W_attn = (const float*)d_in[1];
    const float* b_attn = (const float*)d_in[2];
    const float* W_proj = (const float*)d_in[3];
    const float* b_proj = (const float*)d_in[4];
    float* out = (float*)d_out;

    float* qkv; cudaGetSymbolAddress((void**)&qkv, g_qkv);
    float* yb;  cudaGetSymbolAddress((void**)&yb,  g_y);
    float* xr;  cudaGetSymbolAddress((void**)&xr,  g_xr);
    float* wt;  cudaGetSymbolAddress((void**)&wt,  g_wt);
    float* wt_proj = wt + (size_t)TC3 * C_DIM;

    cudaFuncSetAttribute(flash_attn_mma,
                         cudaFuncAttributeMaxDynamicSharedMemorySize, ATT_SMEM);
    cudaFuncSetAttribute(gemm_tf32_mma,
                         cudaFuncAttributeMaxDynamicSharedMemorySize, GEMM_SMEM);

    // prep: round x to tf32; transpose+round weights
    round_copy_kernel<<<1024, 256>>>(x, xr, (M_ROWS * C_DIM) / 4);
    {
        dim3 blk(32, 8);
        transpose_round_kernel<<<dim3(TC3 / 32, C_DIM / 32), blk>>>(W_attn, wt, C_DIM, TC3);
        transpose_round_kernel<<<dim3(C_DIM / 32, C_DIM / 32), blk>>>(W_proj, wt_proj, C_DIM, C_DIM);
    }

    // 1) QKV = x @ W_attn + b_attn   (tf32 mma.sync, tf32-rounded output)
    gemm_tf32_mma<<<dim3(TC3 / BN, M_ROWS / BM), 256, GEMM_SMEM>>>(
        xr, wt, b_attn, qkv, M_ROWS, TC3, C_DIM, 1);

    // 2) causal flash attention (tensor cores + fast exp2) -> y
    flash_attn_mma<<<dim3(T_SEQ / 128, B_SZ * H_NUM), 256, ATT_SMEM>>>(qkv, yb);

    // 3) out = y @ W_proj + b_proj   (tf32 mma.sync, fp32 output)
    gemm_tf32_mma<<<dim3(C_DIM / BN, M_ROWS / BM), 256, GEMM_SMEM>>>(
        yb, wt_proj, b_proj, out, M_ROWS, C_DIM, C_DIM, 0);
}

// round 7
// speedup vs baseline: 1.0790x; 1.0790x over previous
#include <cuda_runtime.h>
#include <cuda_bf16.h>
#include <cstdint>

// Problem constants
#define C_DIM   1024
#define TC3     3072          // 3*C
#define T_SEQ   2048
#define B_SZ    4
#define H_NUM   16
#define HD      64
#define M_ROWS  (B_SZ * T_SEQ)   // 8192

// Scratch (allocation-free rule: __device__ globals)
__device__ float g_qkv[(size_t)M_ROWS * TC3];          // [B*T, 3C] (tf32-rounded)
__device__ float g_y  [(size_t)M_ROWS * C_DIM];        // [B*T, C] (tf32-rounded)

// ---------------------------------------------------------------------------
// Helpers (arch-portable PTX only: cp.async + mma.sync, both sm_80+)
// ---------------------------------------------------------------------------
__device__ __forceinline__ uint32_t smem_u32(const void* p) {
    uint32_t a;
    asm("{ .reg .u64 t; cvta.to.shared.u64 t, %1; cvt.u32.u64 %0, t; }" : "=r"(a) : "l"(p));
    return a;
}

__device__ __forceinline__ float tf32r(float x) {
    uint32_t r;
    asm("cvt.rn.tf32.f32 %0, %1;" : "=r"(r) : "f"(x));
    return __uint_as_float(r);
}
__device__ __forceinline__ uint32_t tf32r_bits(float x) {
    uint32_t r;
    asm("cvt.rn.tf32.f32 %0, %1;" : "=r"(r) : "f"(x));
    return r;
}

__device__ __forceinline__ void cpasync16(uint32_t s, const void* g) {
    asm volatile("cp.async.cg.shared.global [%0], [%1], 16;" :: "r"(s), "l"(g));
}
#define CP_COMMIT() asm volatile("cp.async.commit_group;" ::: "memory")
#define CP_WAIT(n)  asm volatile("cp.async.wait_group %0;" :: "n"(n) : "memory")

// mma.sync m16n8k8 tf32: D = A*B + C (fp32 accum)
__device__ __forceinline__ void mma_tf32(float* c, const uint32_t* a, const uint32_t* b) {
    asm volatile(
        "mma.sync.aligned.m16n8k8.row.col.f32.tf32.tf32.f32 "
        "{%0,%1,%2,%3}, {%4,%5,%6,%7}, {%8,%9}, {%0,%1,%2,%3};"
        : "+f"(c[0]), "+f"(c[1]), "+f"(c[2]), "+f"(c[3])
        : "r"(a[0]), "r"(a[1]), "r"(a[2]), "r"(a[3]), "r"(b[0]), "r"(b[1]));
}

// Fast exp2 on the FMA pipe (no MUFU). Valid for z <= 0; clamps at -126.
__device__ __forceinline__ float exp2_fast(float z) {
    z = fmaxf(z, -126.f);
    float r = __fadd_rn(z, 12582912.f);            // round z to nearest int
    float f = z - __fadd_rn(r, -12582912.f);       // frac in [-0.5, 0.5]
    int   n = __float_as_int(r) - 0x4B400000;      // integer part
    float p = 1.f + f * (0.69314718f + f * (0.24022651f +
              f * (0.05550411f + f * 0.00961813f)));
    return __int_as_float(__float_as_int(p) + (n << 23));
}

// ---------------------------------------------------------------------------
// tf32 mma.sync GEMM: C[M,N] = A[M,K] @ W[K,N] + bias
//   A: [M,K] fp32 (rounded in-register), W: [K,N] fp32 row-major (NO transpose,
//   rounded in-register). CTA 128x128, 128 threads = 4 warps (2m x 2n),
//   warp tile 64x64. 4-stage cp.async, register fragment double-buffering.
// ---------------------------------------------------------------------------
#define GBM 128
#define GBN 128
#define GBK 16
#define LDSA 20                         // A row stride (floats)
#define LDSB 136                        // B row stride (floats): k-major [16][128+8]
#define GSTG (GBM * LDSA + GBK * LDSB)  // 4736 floats per stage
#define GNS  4
#define GEMM_SMEM (GNS * GSTG * 4)      // 75776 B

__global__ __launch_bounds__(128)
void gemm_tf32_mma(const float* __restrict__ A, const float* __restrict__ W,
                   const float* __restrict__ bias, float* __restrict__ C,
                   int M, int N, int K, int round_out)
{
    extern __shared__ float sm[];
    const int tid  = threadIdx.x;
    const int wid  = tid >> 5;
    const int lane = tid & 31;
    const int wm   = wid & 1;        // 0..1 (64-row slab)
    const int wn   = wid >> 1;       // 0..1 (64-col slab)
    const int m0   = blockIdx.y * GBM;
    const int n0   = blockIdx.x * GBN;
    const int lrow = lane >> 2;      // 0..7
    const int lcol = lane & 3;       // 0..3

    float acc[4][8][4];
    #pragma unroll
    for (int mi = 0; mi < 4; mi++)
        #pragma unroll
        for (int ni = 0; ni < 8; ni++)
            #pragma unroll
            for (int r = 0; r < 4; r++) acc[mi][ni][r] = 0.f;

    const int nkt = K / GBK;

    auto issue = [&](int s, int kt) {
        float* as = sm + s * GSTG;
        float* bs = as + GBM * LDSA;
        const int k0 = kt * GBK;
        // A tile: 128 rows x 16 floats = 512 x 16B chunks
        #pragma unroll
        for (int i = 0; i < 4; i++) {
            int c   = tid + i * 128;
            int row = c >> 2;
            int col = (c & 3) * 4;
            cpasync16(smem_u32(as + row * LDSA + col),
                      A + (size_t)(m0 + row) * K + k0 + col);
        }
        // B tile: 16 k-rows x 128 n-cols = 512 x 16B chunks (direct from W[K,N])
        #pragma unroll
        for (int i = 0; i < 4; i++) {
            int c   = tid + i * 128;
            int row = c >> 5;              // 0..15
            int col = (c & 31) * 4;        // 0..124
            cpasync16(smem_u32(bs + row * LDSB + col),
                      W + (size_t)(k0 + row) * N + n0 + col);
        }
        CP_COMMIT();
    };

    // fragment load (scalar LDS, conflict-free) + in-register tf32 RN rounding
    auto ldfrag = [&](const float* as, const float* bs, int ks,
                      uint32_t af[4][4], uint32_t bf[8][2]) {
        const int kc = ks * 8 + lcol;
        #pragma unroll
        for (int mi = 0; mi < 4; mi++) {
            const float* ap = as + (wm * 64 + mi * 16 + lrow) * LDSA + kc;
            af[mi][0] = tf32r_bits(ap[0]);
            af[mi][1] = tf32r_bits(ap[8 * LDSA]);
            af[mi][2] = tf32r_bits(ap[4]);
            af[mi][3] = tf32r_bits(ap[8 * LDSA + 4]);
        }
        #pragma unroll
        for (int ni = 0; ni < 8; ni++) {
            const float* bp = bs + (size_t)kc * LDSB + wn * 64 + ni * 8 + lrow;
            bf[ni][0] = tf32r_bits(bp[0]);
            bf[ni][1] = tf32r_bits(bp[4 * LDSB]);
        }
    };

    // prologue: 3 stages in flight
    issue(0, 0); issue(1, 1); issue(2, 2);

    uint32_t afA[4][4], bfA[8][2], afB[4][4], bfB[8][2];

    for (int kt = 0; kt < nkt; kt++) {
        const int s = kt & (GNS - 1);
        CP_WAIT(2);                    // group kt landed
        __syncthreads();
        if (kt + 3 < nkt) issue((kt + 3) & (GNS - 1), kt + 3);

        const float* as = sm + s * GSTG;
        const float* bs = as + GBM * LDSA;

        // register double-buffered fragments: load ks=0, then load ks=1
        // BEFORE issuing ks=0 MMAs (hides 29-cyc LDS latency behind tensor work)
        ldfrag(as, bs, 0, afA, bfA);
        ldfrag(as, bs, 1, afB, bfB);

        #pragma unroll
        for (int mi = 0; mi < 4; mi++)
            #pragma unroll
            for (int ni = 0; ni < 8; ni++)
                mma_tf32(acc[mi][ni], afA[mi], bfA[ni]);
        #pragma unroll
        for (int mi = 0; mi < 4; mi++)
            #pragma unroll
            for (int ni = 0; ni < 8; ni++)
                mma_tf32(acc[mi][ni], afB[mi], bfB[ni]);
    }

    // epilogue: bias + store
    #pragma unroll
    for (int mi = 0; mi < 4; mi++) {
        const int row_a = m0 + wm * 64 + mi * 16 + lrow;
        #pragma unroll
        for (int ni = 0; ni < 8; ni++) {
            const int col = n0 + wn * 64 + ni * 8 + lcol * 2;
            const float2 b2 = *reinterpret_cast<const float2*>(&bias[col]);
            float2 o0, o1;
            o0.x = acc[mi][ni][0] + b2.x;
            o0.y = acc[mi][ni][1] + b2.y;
            o1.x = acc[mi][ni][2] + b2.x;
            o1.y = acc[mi][ni][3] + b2.y;
            if (round_out) {
                o0.x = tf32r(o0.x); o0.y = tf32r(o0.y);
                o1.x = tf32r(o1.x); o1.y = tf32r(o1.y);
            }
            *reinterpret_cast<float2*>(&C[(size_t)row_a * N + col])       = o0;
            *reinterpret_cast<float2*>(&C[(size_t)(row_a + 8) * N + col]) = o1;
        }
    }
}

// ---------------------------------------------------------------------------
// Flash attention, tf32 mma.sync + FMA-pipe exp2, causal. (proven R4-R6)
// ---------------------------------------------------------------------------
#define AT_STRIDE 68                     // 64 + 4 pad
#define KV_TILE   (64 * AT_STRIDE)
#define ATT_SMEM  ((4 * KV_TILE + 128 * AT_STRIDE) * 4)

__global__ __launch_bounds__(256, 2)
void flash_attn_mma(const float* __restrict__ qkv, float* __restrict__ y)
{
    extern __shared__ float smf[];
    float* Ksm = smf;                    // [2][64][AT_STRIDE]
    float* Vsm = smf + 2 * KV_TILE;      // [2][64][AT_STRIDE]
    float* PQ  = smf + 4 * KV_TILE;      // [128][AT_STRIDE]

    const int qt = (int)gridDim.x - 1 - (int)blockIdx.x;  // heavy tiles first
    const int bh = blockIdx.y;
    const int b  = bh >> 4;
    const int h  = bh & 15;

    const int tid  = threadIdx.x;
    const int w    = tid >> 5;
    const int lane = tid & 31;
    const int lrow = lane >> 2;
    const int lcol = lane & 3;
    const int w16  = w * 16;

    const float SC = 0.1803368801f;      // 0.125 * log2(e)

    const float* qbase = qkv + (size_t)(b * T_SEQ + qt * 128) * TC3 + h * HD;
    const float* kbase = qkv + (size_t)(b * T_SEQ) * TC3 + C_DIM     + h * HD;
    const float* vbase = qkv + (size_t)(b * T_SEQ) * TC3 + 2 * C_DIM + h * HD;

    const int nkt = 2 * qt + 2;

    auto issue_kv = [&](int kt, int buf) {
        float* kd = Ksm + buf * KV_TILE;
        float* vd = Vsm + buf * KV_TILE;
        const float* ks = kbase + (size_t)(kt * 64) * TC3;
        const float* vs = vbase + (size_t)(kt * 64) * TC3;
        #pragma unroll
        for (int i = 0; i < 4; i++) {
            int c   = tid + i * 256;
            int row = c >> 4;
            int col = (c & 15) * 4;
            cpasync16(smem_u32(kd + row * AT_STRIDE + col), ks + (size_t)row * TC3 + col);
            cpasync16(smem_u32(vd + row * AT_STRIDE + col), vs + (size_t)row * TC3 + col);
        }
        CP_COMMIT();
    };

    #pragma unroll
    for (int i = 0; i < 8; i++) {
        int c   = tid + i * 256;
        int row = c >> 4;
        int col = (c & 15) * 4;
        cpasync16(smem_u32(PQ + row * AT_STRIDE + col), qbase + (size_t)row * TC3 + col);
    }
    CP_COMMIT();
    issue_kv(0, 0);
    CP_WAIT(1);
    __syncthreads();

    uint32_t qf[8][4];
    #pragma unroll
    for (int ks = 0; ks < 8; ks++) {
        const float* q0 = PQ + (w16 + lrow) * AT_STRIDE + ks * 8 + lcol;
        const float* q1 = q0 + 8 * AT_STRIDE;
        qf[ks][0] = __float_as_uint(q0[0]);
        qf[ks][1] = __float_as_uint(q1[0]);
        qf[ks][2] = __float_as_uint(q0[4]);
        qf[ks][3] = __float_as_uint(q1[4]);
    }
    __syncthreads();

    float oacc[8][4];
    #pragma unroll
    for (int nt = 0; nt < 8; nt++)
        #pragma unroll
        for (int r = 0; r < 4; r++) oacc[nt][r] = 0.f;
    float m0 = -1e30f, m1 = -1e30f, l0 = 0.f, l1 = 0.f;

    const int gr0 = qt * 128 + w16 + lrow;
    const int gr1 = gr0 + 8;

    for (int kt = 0; kt < nkt; kt++) {
        const int buf = kt & 1;
        if (kt + 1 < nkt) { issue_kv(kt + 1, buf ^ 1); CP_WAIT(1); }
        else              { CP_WAIT(0); }
        __syncthreads();

        const float* kb = Ksm + buf * KV_TILE;
        const float* vb = Vsm + buf * KV_TILE;

        float s[8][4];
        #pragma unroll
        for (int nt = 0; nt < 8; nt++)
            #pragma unroll
            for (int r = 0; r < 4; r++) s[nt][r] = 0.f;

        #pragma unroll
        for (int ks = 0; ks < 8; ks++) {
            #pragma unroll
            for (int nt = 0; nt < 8; nt++) {
                const float* kp = kb + (nt * 8 + lrow) * AT_STRIDE + ks * 8 + lcol;
                uint32_t bf[2];
                bf[0] = __float_as_uint(kp[0]);
                bf[1] = __float_as_uint(kp[4]);
                mma_tf32(s[nt], qf[ks], bf);
            }
        }

        const bool needmask = (kt >= 2 * qt);
        #pragma unroll
        for (int nt = 0; nt < 8; nt++) {
            const int ck = kt * 64 + nt * 8 + 2 * lcol;
            s[nt][0] *= SC; s[nt][1] *= SC; s[nt][2] *= SC; s[nt][3] *= SC;
            if (needmask) {
                if (ck     > gr0) s[nt][0] = -1e30f;
                if (ck + 1 > gr0) s[nt][1] = -1e30f;
                if (ck     > gr1) s[nt][2] = -1e30f;
                if (ck + 1 > gr1) s[nt][3] = -1e30f;
            }
        }

        float mx0 = -1e30f, mx1 = -1e30f;
        #pragma unroll
        for (int nt = 0; nt < 8; nt++) {
            mx0 = fmaxf(mx0, fmaxf(s[nt][0], s[nt][1]));
            mx1 = fmaxf(mx1, fmaxf(s[nt][2], s[nt][3]));
        }
        mx0 = fmaxf(mx0, __shfl_xor_sync(0xffffffffu, mx0, 1));
        mx0 = fmaxf(mx0, __shfl_xor_sync(0xffffffffu, mx0, 2));
        mx1 = fmaxf(mx1, __shfl_xor_sync(0xffffffffu, mx1, 1));
        mx1 = fmaxf(mx1, __shfl_xor_sync(0xffffffffu, mx1, 2));

        const float mn0 = fmaxf(m0, mx0);
        const float mn1 = fmaxf(m1, mx1);
        const float a0  = exp2_fast(m0 - mn0);
        const float a1  = exp2_fast(m1 - mn1);
        m0 = mn0; m1 = mn1;

        float rs0 = 0.f, rs1 = 0.f;
        #pragma unroll
        for (int nt = 0; nt < 8; nt++) {
            s[nt][0] = exp2_fast(s[nt][0] - mn0);
            s[nt][1] = exp2_fast(s[nt][1] - mn0);
            s[nt][2] = exp2_fast(s[nt][2] - mn1);
            s[nt][3] = exp2_fast(s[nt][3] - mn1);
            rs0 += s[nt][0] + s[nt][1];
            rs1 += s[nt][2] + s[nt][3];
        }
        rs0 += __shfl_xor_sync(0xffffffffu, rs0, 1);
        rs0 += __shfl_xor_sync(0xffffffffu, rs0, 2);
        rs1 += __shfl_xor_sync(0xffffffffu, rs1, 1);
        rs1 += __shfl_xor_sync(0xffffffffu, rs1, 2);
        l0 = l0 * a0 + rs0;
        l1 = l1 * a1 + rs1;

        #pragma unroll
        for (int nt = 0; nt < 8; nt++) {
            oacc[nt][0] *= a0; oacc[nt][1] *= a0;
            oacc[nt][2] *= a1; oacc[nt][3] *= a1;
        }

        #pragma unroll
        for (int nt = 0; nt < 8; nt++) {
            float* p0 = PQ + (w16 + lrow) * AT_STRIDE + nt * 8 + 2 * lcol;
            *reinterpret_cast<float2*>(p0) =
                make_float2(tf32r(s[nt][0]), tf32r(s[nt][1]));
            *reinterpret_cast<float2*>(p0 + 8 * AT_STRIDE) =
                make_float2(tf32r(s[nt][2]), tf32r(s[nt][3]));
        }
        __syncwarp();

        #pragma unroll
        for (int ks = 0; ks < 8; ks++) {
            uint32_t af[4];
            const float* p0 = PQ + (w16 + lrow) * AT_STRIDE + ks * 8 + lcol;
            const float* p1 = p0 + 8 * AT_STRIDE;
            af[0] = __float_as_uint(p0[0]);
            af[1] = __float_as_uint(p1[0]);
            af[2] = __float_as_uint(p0[4]);
            af[3] = __float_as_uint(p1[4]);
            #pragma unroll
            for (int nt = 0; nt < 8; nt++) {
                const float* vp = vb + (ks * 8 + lcol) * AT_STRIDE + nt * 8 + lrow;
                uint32_t bf[2];
                bf[0] = __float_as_uint(vp[0]);
                bf[1] = __float_as_uint(vp[4 * AT_STRIDE]);
                mma_tf32(oacc[nt], af, bf);
            }
        }
        __syncthreads();
    }

    const float inv0 = 1.f / l0;
    const float inv1 = 1.f / l1;
    float* y0 = y + (size_t)(b * T_SEQ + gr0) * C_DIM + h * HD;
    #pragma unroll
    for (int nt = 0; nt < 8; nt++) {
        const int col = nt * 8 + 2 * lcol;
        *reinterpret_cast<float2*>(y0 + (size_t)0 * C_DIM + col) =
            make_float2(tf32r(oacc[nt][0] * inv0), tf32r(oacc[nt][1] * inv0));
        *reinterpret_cast<float2*>(y0 + (size_t)8 * C_DIM + col) =
            make_float2(tf32r(oacc[nt][2] * inv1), tf32r(oacc[nt][3] * inv1));
    }
}

// ---------------------------------------------------------------------------
extern "C" void kernel_launch(void* const* d_in, const int* in_sizes, int n_in,
                              void* d_out, int out_size)
{
    const float* x      = (const float*)d_in[0];   // [4,2048,1024]
    const float* W_attn = (const float*)d_in[1];   // [1024,3072]
    const float* b_attn = (const float*)d_in[2];   // [3072]
    const float* W_proj = (const float*)d_in[3];   // [1024,1024]
    const float* b_proj = (const float*)d_in[4];   // [1024]
    float* out = (float*)d_out;                    // [4,2048,1024]

    float* qkv; cudaGetSymbolAddress((void**)&qkv, g_qkv);
    float* yb;  cudaGetSymbolAddress((void**)&yb,  g_y);

    cudaFuncSetAttribute(flash_attn_mma,
                         cudaFuncAttributeMaxDynamicSharedMemorySize, ATT_SMEM);
    cudaFuncSetAttribute(gemm_tf32_mma,
                         cudaFuncAttributeMaxDynamicSharedMemorySize, GEMM_SMEM);

    // 1) QKV = x @ W_attn + b_attn   (tf32 mma.sync; inputs rounded in-register)
    gemm_tf32_mma<<<dim3(TC3 / GBN, M_ROWS / GBM), 128, GEMM_SMEM>>>(
        x, W_attn, b_attn, qkv, M_ROWS, TC3, C_DIM, 1);

    // 2) causal flash attention (tensor cores + fast exp2) -> y
    flash_attn_mma<<<dim3(T_SEQ / 128, B_SZ * H_NUM), 256, ATT_SMEM>>>(qkv, yb);

    // 3) out = y @ W_proj + b_proj
    gemm_tf32_mma<<<dim3(C_DIM / GBN, M_ROWS / GBM), 128, GEMM_SMEM>>>(
        yb, W_proj, b_proj, out, M_ROWS, C_DIM, C_DIM, 0);
}